// round 1
// baseline (speedup 1.0000x reference)
#include <cuda_runtime.h>
#include <math.h>

#define B_ 8
#define C_ 2048
#define F_ 512
#define THRESH 0.005f

// ---- scratch (device globals: no allocation allowed) ----
__device__ float g_A[(size_t)B_ * C_ * C_];      // binary adjacency, 134 MB
__device__ float g_invnorm[B_ * C_];
__device__ float g_dinv[B_ * C_];
__device__ float g_hs[(size_t)B_ * C_ * F_];     // d^{-1/2}-scaled h
__device__ float g_lx[(size_t)B_ * C_ * F_];     // L @ h
__device__ float g_h2[(size_t)B_ * C_ * F_];     // hidden activations

// ---------------------------------------------------------------------------
// 1) row inverse norms: invn[b,c] = 1/sqrt(sum_f x^2)
// ---------------------------------------------------------------------------
__global__ void norm_kernel(const float* __restrict__ x, float* __restrict__ invn) {
    int row = blockIdx.x;                  // B_*C_ rows
    const float* xr = x + (size_t)row * F_;
    float s = 0.f;
    for (int i = threadIdx.x; i < F_; i += 128) { float v = xr[i]; s += v * v; }
    __shared__ float red[128];
    red[threadIdx.x] = s; __syncthreads();
    for (int o = 64; o > 0; o >>= 1) {
        if (threadIdx.x < o) red[threadIdx.x] += red[threadIdx.x + o];
        __syncthreads();
    }
    if (threadIdx.x == 0) invn[row] = 1.0f / sqrtf(red[0]);
}

// ---------------------------------------------------------------------------
// 2) Gram X·X^T, normalize by invnorms, threshold -> binary adjacency
//    per batch: M=N=C_, K=F_. 128x128 tile, 8x8 per thread.
// ---------------------------------------------------------------------------
__global__ __launch_bounds__(256) void gram_kernel(const float* __restrict__ x,
                                                   const float* __restrict__ invn,
                                                   float* __restrict__ Aout) {
    int b = blockIdx.z;
    const float* X = x + (size_t)b * C_ * F_;
    float* Ab = Aout + (size_t)b * C_ * C_;
    const float* inb = invn + b * C_;
    int m0 = blockIdx.y * 128, n0 = blockIdx.x * 128;

    __shared__ float As[8][128];
    __shared__ float Bs[8][128];

    int tid = threadIdx.x;
    int lr = tid >> 1, lk = (tid & 1) * 4;      // loader: row in tile, k offset
    int tr = (tid >> 4) * 8, tc = (tid & 15) * 8;

    float acc[8][8];
#pragma unroll
    for (int i = 0; i < 8; i++)
#pragma unroll
        for (int j = 0; j < 8; j++) acc[i][j] = 0.f;

    for (int k0 = 0; k0 < F_; k0 += 8) {
        float4 a4 = *(const float4*)(X + (size_t)(m0 + lr) * F_ + k0 + lk);
        float4 b4 = *(const float4*)(X + (size_t)(n0 + lr) * F_ + k0 + lk);
        As[lk + 0][lr] = a4.x; As[lk + 1][lr] = a4.y; As[lk + 2][lr] = a4.z; As[lk + 3][lr] = a4.w;
        Bs[lk + 0][lr] = b4.x; Bs[lk + 1][lr] = b4.y; Bs[lk + 2][lr] = b4.z; Bs[lk + 3][lr] = b4.w;
        __syncthreads();
#pragma unroll
        for (int kk = 0; kk < 8; kk++) {
            float ar[8], br[8];
            *(float4*)&ar[0] = *(const float4*)&As[kk][tr];
            *(float4*)&ar[4] = *(const float4*)&As[kk][tr + 4];
            *(float4*)&br[0] = *(const float4*)&Bs[kk][tc];
            *(float4*)&br[4] = *(const float4*)&Bs[kk][tc + 4];
#pragma unroll
            for (int i = 0; i < 8; i++)
#pragma unroll
                for (int j = 0; j < 8; j++) acc[i][j] += ar[i] * br[j];
        }
        __syncthreads();
    }

    float im[8], jn[8];
#pragma unroll
    for (int i = 0; i < 8; i++) im[i] = inb[m0 + tr + i];
#pragma unroll
    for (int j = 0; j < 8; j++) jn[j] = inb[n0 + tc + j];

#pragma unroll
    for (int i = 0; i < 8; i++) {
        float o[8];
#pragma unroll
        for (int j = 0; j < 8; j++) {
            float c = acc[i][j] * im[i] * jn[j];
            o[j] = (c > THRESH) ? 1.f : 0.f;
        }
        float* dst = Ab + (size_t)(m0 + tr + i) * C_ + n0 + tc;
        *(float4*)dst       = make_float4(o[0], o[1], o[2], o[3]);
        *(float4*)(dst + 4) = make_float4(o[4], o[5], o[6], o[7]);
    }
}

// ---------------------------------------------------------------------------
// 3) degrees -> d^{-1/2}
// ---------------------------------------------------------------------------
__global__ void deg_kernel(const float* __restrict__ A, float* __restrict__ dinv) {
    int row = blockIdx.x;                 // B_*C_ rows
    const float* Ar = A + (size_t)row * C_;
    float s = 0.f;
    for (int i = threadIdx.x; i < C_; i += 256) s += Ar[i];
    __shared__ float red[256];
    red[threadIdx.x] = s; __syncthreads();
    for (int o = 128; o > 0; o >>= 1) {
        if (threadIdx.x < o) red[threadIdx.x] += red[threadIdx.x + o];
        __syncthreads();
    }
    if (threadIdx.x == 0) dinv[row] = 1.0f / sqrtf(red[0]);
}

// ---------------------------------------------------------------------------
// 4) h'[b,c,f] = dinv[b,c] * h[b,c,f]   (float4 over B*C*F/4)
// ---------------------------------------------------------------------------
__global__ void scale_kernel(const float* __restrict__ h,
                             const float* __restrict__ dinv,
                             float* __restrict__ out) {
    size_t idx = (size_t)blockIdx.x * blockDim.x + threadIdx.x;   // float4 index
    float4 v = ((const float4*)h)[idx];
    float d = dinv[idx / (F_ / 4)];
    v.x *= d; v.y *= d; v.z *= d; v.w *= d;
    ((float4*)out)[idx] = v;
}

// ---------------------------------------------------------------------------
// 5) lx = dinv[row] * (A @ h')   per batch: M=C_, N=F_, K=C_
// ---------------------------------------------------------------------------
__global__ __launch_bounds__(256) void gemm_AH(const float* __restrict__ Aadj,
                                               const float* __restrict__ hp,
                                               const float* __restrict__ dinv,
                                               float* __restrict__ out) {
    int b = blockIdx.z;
    const float* Ab = Aadj + (size_t)b * C_ * C_;
    const float* Hb = hp + (size_t)b * C_ * F_;
    float* Ob = out + (size_t)b * C_ * F_;
    const float* db = dinv + b * C_;
    int m0 = blockIdx.y * 128, n0 = blockIdx.x * 128;

    __shared__ float As[8][128];
    __shared__ float Bs[8][128];

    int tid = threadIdx.x;
    int lr = tid >> 1, lk = (tid & 1) * 4;        // A loader (transpose along k)
    int bk = tid >> 5, bn = (tid & 31) * 4;       // B loader (direct)
    int tr = (tid >> 4) * 8, tc = (tid & 15) * 8;

    float acc[8][8];
#pragma unroll
    for (int i = 0; i < 8; i++)
#pragma unroll
        for (int j = 0; j < 8; j++) acc[i][j] = 0.f;

    for (int k0 = 0; k0 < C_; k0 += 8) {
        float4 a4 = *(const float4*)(Ab + (size_t)(m0 + lr) * C_ + k0 + lk);
        float4 b4 = *(const float4*)(Hb + (size_t)(k0 + bk) * F_ + n0 + bn);
        As[lk + 0][lr] = a4.x; As[lk + 1][lr] = a4.y; As[lk + 2][lr] = a4.z; As[lk + 3][lr] = a4.w;
        *(float4*)&Bs[bk][bn] = b4;
        __syncthreads();
#pragma unroll
        for (int kk = 0; kk < 8; kk++) {
            float ar[8], br[8];
            *(float4*)&ar[0] = *(const float4*)&As[kk][tr];
            *(float4*)&ar[4] = *(const float4*)&As[kk][tr + 4];
            *(float4*)&br[0] = *(const float4*)&Bs[kk][tc];
            *(float4*)&br[4] = *(const float4*)&Bs[kk][tc + 4];
#pragma unroll
            for (int i = 0; i < 8; i++)
#pragma unroll
                for (int j = 0; j < 8; j++) acc[i][j] += ar[i] * br[j];
        }
        __syncthreads();
    }

#pragma unroll
    for (int i = 0; i < 8; i++) {
        float d = db[m0 + tr + i];
        float o[8];
#pragma unroll
        for (int j = 0; j < 8; j++) o[j] = acc[i][j] * d;
        float* dst = Ob + (size_t)(m0 + tr + i) * F_ + n0 + tc;
        *(float4*)dst       = make_float4(o[0], o[1], o[2], o[3]);
        *(float4*)(dst + 4) = make_float4(o[4], o[5], o[6], o[7]);
    }
}

// ---------------------------------------------------------------------------
// 6) out = relu(H @ W + b)   flat M = B_*C_, N = F_, K = F_
// ---------------------------------------------------------------------------
__global__ __launch_bounds__(256) void gemm_HW(const float* __restrict__ H,
                                               const float* __restrict__ W,
                                               const float* __restrict__ bias,
                                               float* __restrict__ out) {
    int m0 = blockIdx.y * 128, n0 = blockIdx.x * 128;

    __shared__ float As[8][128];
    __shared__ float Bs[8][128];

    int tid = threadIdx.x;
    int lr = tid >> 1, lk = (tid & 1) * 4;
    int bk = tid >> 5, bn = (tid & 31) * 4;
    int tr = (tid >> 4) * 8, tc = (tid & 15) * 8;

    float acc[8][8];
#pragma unroll
    for (int i = 0; i < 8; i++)
#pragma unroll
        for (int j = 0; j < 8; j++) acc[i][j] = 0.f;

    for (int k0 = 0; k0 < F_; k0 += 8) {
        float4 a4 = *(const float4*)(H + (size_t)(m0 + lr) * F_ + k0 + lk);
        float4 b4 = *(const float4*)(W + (size_t)(k0 + bk) * F_ + n0 + bn);
        As[lk + 0][lr] = a4.x; As[lk + 1][lr] = a4.y; As[lk + 2][lr] = a4.z; As[lk + 3][lr] = a4.w;
        *(float4*)&Bs[bk][bn] = b4;
        __syncthreads();
#pragma unroll
        for (int kk = 0; kk < 8; kk++) {
            float ar[8], br[8];
            *(float4*)&ar[0] = *(const float4*)&As[kk][tr];
            *(float4*)&ar[4] = *(const float4*)&As[kk][tr + 4];
            *(float4*)&br[0] = *(const float4*)&Bs[kk][tc];
            *(float4*)&br[4] = *(const float4*)&Bs[kk][tc + 4];
#pragma unroll
            for (int i = 0; i < 8; i++)
#pragma unroll
                for (int j = 0; j < 8; j++) acc[i][j] += ar[i] * br[j];
        }
        __syncthreads();
    }

    float bb = bias[0];
#pragma unroll
    for (int i = 0; i < 8; i++) {
        float o[8];
#pragma unroll
        for (int j = 0; j < 8; j++) o[j] = fmaxf(acc[i][j] + bb, 0.f);
        float* dst = out + (size_t)(m0 + tr + i) * F_ + n0 + tc;
        *(float4*)dst       = make_float4(o[0], o[1], o[2], o[3]);
        *(float4*)(dst + 4) = make_float4(o[4], o[5], o[6], o[7]);
    }
}

// ---------------------------------------------------------------------------
extern "C" void kernel_launch(void* const* d_in, const int* in_sizes, int n_in,
                              void* d_out, int out_size) {
    const float* x  = (const float*)d_in[0];
    const float* W1 = (const float*)d_in[1];
    const float* b1 = (const float*)d_in[2];
    const float* W2 = (const float*)d_in[3];
    const float* b2 = (const float*)d_in[4];
    float* out = (float*)d_out;

    float *pA, *pinv, *pdinv, *phs, *plx, *ph2;
    cudaGetSymbolAddress((void**)&pA,    g_A);
    cudaGetSymbolAddress((void**)&pinv,  g_invnorm);
    cudaGetSymbolAddress((void**)&pdinv, g_dinv);
    cudaGetSymbolAddress((void**)&phs,   g_hs);
    cudaGetSymbolAddress((void**)&plx,   g_lx);
    cudaGetSymbolAddress((void**)&ph2,   g_h2);

    const int scale_blocks = (B_ * C_ * F_ / 4) / 256;   // 8192

    // Laplacian pieces
    norm_kernel<<<B_ * C_, 128>>>(x, pinv);
    gram_kernel<<<dim3(C_ / 128, C_ / 128, B_), 256>>>(x, pinv, pA);
    deg_kernel<<<B_ * C_, 256>>>(pA, pdinv);

    // layer 1
    scale_kernel<<<scale_blocks, 256>>>(x, pdinv, phs);
    gemm_AH<<<dim3(F_ / 128, C_ / 128, B_), 256>>>(pA, phs, pdinv, plx);
    gemm_HW<<<dim3(F_ / 128, (B_ * C_) / 128), 256>>>(plx, W1, b1, ph2);

    // layer 2
    scale_kernel<<<scale_blocks, 256>>>(ph2, pdinv, phs);
    gemm_AH<<<dim3(F_ / 128, C_ / 128, B_), 256>>>(pA, phs, pdinv, plx);
    gemm_HW<<<dim3(F_ / 128, (B_ * C_) / 128), 256>>>(plx, W2, b2, out);
}

// round 3
// speedup vs baseline: 1.5756x; 1.5756x over previous
#include <cuda_runtime.h>
#include <cstdint>
#include <math.h>

#define B_ 8
#define C_ 2048
#define F_ 512
#define THRESH 0.005f

// ---- scratch (device globals: no allocation allowed) ----
__device__ float g_A[(size_t)B_ * C_ * C_];        // binary adjacency (fp32 0/1)
__device__ float g_invn[B_ * C_];
__device__ float g_dinv[B_ * C_];
__device__ float g_xhi[(size_t)B_ * C_ * F_];
__device__ float g_xlo[(size_t)B_ * C_ * F_];
__device__ float g_hT_hi[(size_t)B_ * F_ * C_];    // (dinv*h)^T split
__device__ float g_hT_lo[(size_t)B_ * F_ * C_];
__device__ float g_lx_hi[(size_t)B_ * C_ * F_];    // L@h split
__device__ float g_lx_lo[(size_t)B_ * C_ * F_];
__device__ float g_h2[(size_t)B_ * C_ * F_];       // hidden activations
__device__ float g_WT_hi[F_ * F_];
__device__ float g_WT_lo[F_ * F_];

// =============================== helpers ===============================
__device__ __forceinline__ uint32_t smem_u32(const void* p) {
    uint32_t a;
    asm("{ .reg .u64 t; cvta.to.shared.u64 t, %1; cvt.u32.u64 %0, t; }" : "=r"(a) : "l"(p));
    return a;
}
__device__ __forceinline__ float f2tf32(float v) {
    uint32_t u;
    asm("cvt.rna.tf32.f32 %0, %1;" : "=r"(u) : "f"(v));
    return __uint_as_float(u);
}
#define CP_COMMIT() asm volatile("cp.async.commit_group;" ::: "memory")
#define CP_WAIT1()  asm volatile("cp.async.wait_group 1;" ::: "memory")
#define CP_WAIT0()  asm volatile("cp.async.wait_group 0;" ::: "memory")

__device__ __forceinline__ void mma_tf32(float c[4], const uint32_t a[4], const uint32_t b[2]) {
    asm volatile(
        "mma.sync.aligned.m16n8k8.row.col.f32.tf32.tf32.f32 "
        "{%0,%1,%2,%3}, {%4,%5,%6,%7}, {%8,%9}, {%0,%1,%2,%3};"
        : "+f"(c[0]), "+f"(c[1]), "+f"(c[2]), "+f"(c[3])
        : "r"(a[0]), "r"(a[1]), "r"(a[2]), "r"(a[3]), "r"(b[0]), "r"(b[1]));
}

// ====================== tf32 mma.sync GEMM (128x128 tile) ======================
// Layouts: all operands row-major with K contiguous:
//   Aop[m][k] (lda), Bop[n][k] (ldb)  -> mma row.col direct fit.
// MODE 0: GRAM  acc = xhi·xhiT + xhi·xloT + xlo·xhiT ; epi: binarize corr
// MODE 1: AH    acc = A·hThiT + A·hTloT             ; epi: *dinv[m], split hi/lo
// MODE 2: HW    acc = 3-pass split                  ; epi: relu(+bias)
#define KC 32                 // K per chunk
#define TSTRIDE 36            // smem row stride (conflict-free: 4*row+col distinct)
#define TE (128 * TSTRIDE)    // floats per tile

template <int MODE>
__global__ __launch_bounds__(256) void mma_gemm(
    const float* __restrict__ a0, const float* __restrict__ a1,
    const float* __restrict__ b0, const float* __restrict__ b1,
    int lda, int ldb, int K,
    size_t aBatch, size_t bBatch,
    const float* __restrict__ aux, int auxBatch,
    float* __restrict__ out0, float* __restrict__ out1,
    int ldo, size_t oBatch)
{
    constexpr int NA = (MODE == 1) ? 1 : 2;
    constexpr int NOPS = NA + 2;

    int m0 = blockIdx.y * 128, n0 = blockIdx.x * 128, b = blockIdx.z;
    int tid = threadIdx.x, wid = tid >> 5, lane = tid & 31;
    int wm = wid & 1, wn = wid >> 1;          // warp tile: 64x32 at (wm*64, wn*32)
    int g = lane >> 2, t = lane & 3;

    const float* ops[NOPS];
    int ldv[NOPS];
    ops[0] = a0 + (size_t)b * aBatch + (size_t)m0 * lda; ldv[0] = lda;
    if (NA == 2) { ops[1] = a1 + (size_t)b * aBatch + (size_t)m0 * lda; ldv[1] = lda; }
    ops[NA]     = b0 + (size_t)b * bBatch + (size_t)n0 * ldb; ldv[NA] = ldb;
    ops[NA + 1] = b1 + (size_t)b * bBatch + (size_t)n0 * ldb; ldv[NA + 1] = ldb;

    extern __shared__ float sm[];

    auto load_tile = [&](int op, int buf, int k0) {
        float* dst = sm + (size_t)(buf * NOPS + op) * TE;
        const float* src = ops[op] + k0;
        int ld = ldv[op];
#pragma unroll
        for (int i = 0; i < 4; i++) {
            int idx = tid + i * 256;
            int row = idx >> 3, seg = idx & 7;
            const float* gp = src + (size_t)row * ld + seg * 4;
            uint32_t sa = smem_u32(dst + row * TSTRIDE + seg * 4);
            asm volatile("cp.async.cg.shared.global [%0], [%1], 16;" :: "r"(sa), "l"(gp) : "memory");
        }
    };

    float acc[4][4][4];
#pragma unroll
    for (int i = 0; i < 4; i++)
#pragma unroll
        for (int j = 0; j < 4; j++)
#pragma unroll
            for (int r = 0; r < 4; r++) acc[i][j][r] = 0.f;

    uint32_t afr[2][4][4];     // [which A operand][mtile][reg]
    uint32_t bfr[2][4][2];     // [which B operand][ntile][reg]

    auto lda_frag = [&](int op, int buf, int kk, int slot) {
        const float* T = sm + (size_t)(buf * NOPS + op) * TE;
#pragma unroll
        for (int i = 0; i < 4; i++) {
            int r = wm * 64 + i * 16 + g;
            afr[slot][i][0] = __float_as_uint(T[r * TSTRIDE + kk + t]);
            afr[slot][i][1] = __float_as_uint(T[(r + 8) * TSTRIDE + kk + t]);
            afr[slot][i][2] = __float_as_uint(T[r * TSTRIDE + kk + t + 4]);
            afr[slot][i][3] = __float_as_uint(T[(r + 8) * TSTRIDE + kk + t + 4]);
        }
    };
    auto ldb_frag = [&](int op, int buf, int kk, int slot) {
        const float* T = sm + (size_t)(buf * NOPS + NA + op) * TE;
#pragma unroll
        for (int j = 0; j < 4; j++) {
            int n = wn * 32 + j * 8 + g;
            bfr[slot][j][0] = __float_as_uint(T[n * TSTRIDE + kk + t]);
            bfr[slot][j][1] = __float_as_uint(T[n * TSTRIDE + kk + t + 4]);
        }
    };
    auto mma_pass = [&](int aslot, int bslot) {
#pragma unroll
        for (int i = 0; i < 4; i++)
#pragma unroll
            for (int j = 0; j < 4; j++)
                mma_tf32(acc[i][j], afr[aslot][i], bfr[bslot][j]);
    };

    const int NC = K / KC;
    for (int op = 0; op < NOPS; op++) load_tile(op, 0, 0);
    CP_COMMIT();

    for (int c = 0; c < NC; c++) {
        int buf = c & 1;
        if (c + 1 < NC) {
            for (int op = 0; op < NOPS; op++) load_tile(op, (c + 1) & 1, (c + 1) * KC);
            CP_COMMIT();
            CP_WAIT1();
        } else {
            CP_WAIT0();
        }
        __syncthreads();
#pragma unroll
        for (int ks = 0; ks < KC / 8; ks++) {
            int kk = ks * 8;
            lda_frag(0, buf, kk, 0);
            ldb_frag(0, buf, kk, 0);
            mma_pass(0, 0);                  // A0 * B0
            ldb_frag(1, buf, kk, 1);
            mma_pass(0, 1);                  // A0 * B1
            if (MODE != 1) {
                lda_frag(1, buf, kk, 1);
                mma_pass(1, 0);              // A1 * B0
            }
        }
        __syncthreads();
    }

    // ------------------------------- epilogue -------------------------------
    float bias = (MODE == 2) ? aux[0] : 0.f;
#pragma unroll
    for (int i = 0; i < 4; i++) {
        int row0 = m0 + wm * 64 + i * 16 + g;
        int row1 = row0 + 8;
        float rs0 = 0.f, rs1 = 0.f;
        if (MODE == 0 || MODE == 1) {
            rs0 = aux[(size_t)b * auxBatch + row0];
            rs1 = aux[(size_t)b * auxBatch + row1];
        }
#pragma unroll
        for (int j = 0; j < 4; j++) {
            int col = n0 + wn * 32 + j * 8 + t * 2;
            float v00 = acc[i][j][0], v01 = acc[i][j][1];
            float v10 = acc[i][j][2], v11 = acc[i][j][3];
            if (MODE == 0) {
                float jn0 = aux[(size_t)b * auxBatch + col];
                float jn1 = aux[(size_t)b * auxBatch + col + 1];
                v00 = (v00 * rs0 * jn0 > THRESH) ? 1.f : 0.f;
                v01 = (v01 * rs0 * jn1 > THRESH) ? 1.f : 0.f;
                v10 = (v10 * rs1 * jn0 > THRESH) ? 1.f : 0.f;
                v11 = (v11 * rs1 * jn1 > THRESH) ? 1.f : 0.f;
            } else if (MODE == 1) {
                v00 *= rs0; v01 *= rs0; v10 *= rs1; v11 *= rs1;
            } else {
                v00 = fmaxf(v00 + bias, 0.f); v01 = fmaxf(v01 + bias, 0.f);
                v10 = fmaxf(v10 + bias, 0.f); v11 = fmaxf(v11 + bias, 0.f);
            }
            float* p0 = out0 + (size_t)b * oBatch + (size_t)row0 * ldo + col;
            float* p1 = out0 + (size_t)b * oBatch + (size_t)row1 * ldo + col;
            if (MODE == 1) {
                float h00 = f2tf32(v00), h01 = f2tf32(v01);
                float h10 = f2tf32(v10), h11 = f2tf32(v11);
                *(float2*)p0 = make_float2(h00, h01);
                *(float2*)p1 = make_float2(h10, h11);
                float* q0 = out1 + (size_t)b * oBatch + (size_t)row0 * ldo + col;
                float* q1 = out1 + (size_t)b * oBatch + (size_t)row1 * ldo + col;
                *(float2*)q0 = make_float2(f2tf32(v00 - h00), f2tf32(v01 - h01));
                *(float2*)q1 = make_float2(f2tf32(v10 - h10), f2tf32(v11 - h11));
            } else {
                *(float2*)p0 = make_float2(v00, v01);
                *(float2*)p1 = make_float2(v10, v11);
            }
        }
    }
}

// =============================== small kernels ==============================
__global__ void norm_kernel(const float* __restrict__ x, float* __restrict__ invn) {
    int row = blockIdx.x;
    const float* xr = x + (size_t)row * F_;
    float s = 0.f;
    for (int i = threadIdx.x; i < F_; i += 128) { float v = xr[i]; s += v * v; }
    __shared__ float red[128];
    red[threadIdx.x] = s; __syncthreads();
    for (int o = 64; o > 0; o >>= 1) {
        if (threadIdx.x < o) red[threadIdx.x] += red[threadIdx.x + o];
        __syncthreads();
    }
    if (threadIdx.x == 0) invn[row] = 1.0f / sqrtf(red[0]);
}

__global__ void split_kernel(const float* __restrict__ x,
                             float* __restrict__ hi, float* __restrict__ lo) {
    size_t i = (size_t)blockIdx.x * 256 + threadIdx.x;
    float v = x[i];
    float h = f2tf32(v);
    hi[i] = h;
    lo[i] = f2tf32(v - h);
}

__global__ void deg_kernel(const float* __restrict__ A, float* __restrict__ dinv) {
    int row = blockIdx.x;
    const float* Ar = A + (size_t)row * C_;
    float s = 0.f;
    for (int i = threadIdx.x; i < C_; i += 256) s += Ar[i];
    __shared__ float red[256];
    red[threadIdx.x] = s; __syncthreads();
    for (int o = 128; o > 0; o >>= 1) {
        if (threadIdx.x < o) red[threadIdx.x] += red[threadIdx.x + o];
        __syncthreads();
    }
    if (threadIdx.x == 0) dinv[row] = 1.0f / sqrtf(red[0]);
}

// h[b,c,f] * dinv[b,c]  ->  transposed split hT_hi/lo [b,f,c]
__global__ void scale_transpose(const float* __restrict__ h, const float* __restrict__ dinv,
                                float* __restrict__ thi, float* __restrict__ tlo) {
    __shared__ float tsm[32][33];
    int c0 = blockIdx.x * 32, f0 = blockIdx.y * 32, b = blockIdx.z;
    const float* hb = h + (size_t)b * C_ * F_;
#pragma unroll
    for (int k = 0; k < 4; k++) {
        int c = c0 + threadIdx.y + k * 8;
        float v = hb[(size_t)c * F_ + f0 + threadIdx.x] * dinv[b * C_ + c];
        tsm[threadIdx.x][threadIdx.y + k * 8] = v;
    }
    __syncthreads();
#pragma unroll
    for (int k = 0; k < 4; k++) {
        int f = f0 + threadIdx.y + k * 8;
        float v = tsm[threadIdx.y + k * 8][threadIdx.x];
        float hi = f2tf32(v);
        size_t o = (size_t)b * F_ * C_ + (size_t)f * C_ + c0 + threadIdx.x;
        thi[o] = hi;
        tlo[o] = f2tf32(v - hi);
    }
}

// W[f,g] -> WT[g,f] split
__global__ void wtrans_kernel(const float* __restrict__ W,
                              float* __restrict__ hi, float* __restrict__ lo) {
    __shared__ float tsm[32][33];
    int g0 = blockIdx.x * 32, f0 = blockIdx.y * 32;
#pragma unroll
    for (int k = 0; k < 4; k++) {
        int f = f0 + threadIdx.y + k * 8;
        tsm[threadIdx.x][threadIdx.y + k * 8] = W[(size_t)f * F_ + g0 + threadIdx.x];
    }
    __syncthreads();
#pragma unroll
    for (int k = 0; k < 4; k++) {
        int g = g0 + threadIdx.y + k * 8;
        float v = tsm[threadIdx.y + k * 8][threadIdx.x];
        float h = f2tf32(v);
        size_t o = (size_t)g * F_ + f0 + threadIdx.x;
        hi[o] = h;
        lo[o] = f2tf32(v - h);
    }
}

// ============================================================================
extern "C" void kernel_launch(void* const* d_in, const int* in_sizes, int n_in,
                              void* d_out, int out_size) {
    const float* x  = (const float*)d_in[0];
    const float* W1 = (const float*)d_in[1];
    const float* b1 = (const float*)d_in[2];
    const float* W2 = (const float*)d_in[3];
    const float* b2 = (const float*)d_in[4];
    float* out = (float*)d_out;

    float *pA, *pinvn, *pdinv, *pxhi, *pxlo, *phThi, *phTlo, *plxhi, *plxlo, *ph2, *pWThi, *pWTlo;
    cudaGetSymbolAddress((void**)&pA,    g_A);
    cudaGetSymbolAddress((void**)&pinvn, g_invn);
    cudaGetSymbolAddress((void**)&pdinv, g_dinv);
    cudaGetSymbolAddress((void**)&pxhi,  g_xhi);
    cudaGetSymbolAddress((void**)&pxlo,  g_xlo);
    cudaGetSymbolAddress((void**)&phThi, g_hT_hi);
    cudaGetSymbolAddress((void**)&phTlo, g_hT_lo);
    cudaGetSymbolAddress((void**)&plxhi, g_lx_hi);
    cudaGetSymbolAddress((void**)&plxlo, g_lx_lo);
    cudaGetSymbolAddress((void**)&ph2,   g_h2);
    cudaGetSymbolAddress((void**)&pWThi, g_WT_hi);
    cudaGetSymbolAddress((void**)&pWTlo, g_WT_lo);

    const int smem4 = 4 * 2 * TE * 4;   // GRAM / HW: 4 operands, double buffered
    const int smem3 = 3 * 2 * TE * 4;   // AH: 3 operands
    cudaFuncSetAttribute(mma_gemm<0>, cudaFuncAttributeMaxDynamicSharedMemorySize, smem4);
    cudaFuncSetAttribute(mma_gemm<1>, cudaFuncAttributeMaxDynamicSharedMemorySize, smem3);
    cudaFuncSetAttribute(mma_gemm<2>, cudaFuncAttributeMaxDynamicSharedMemorySize, smem4);

    // ---- Laplacian ----
    norm_kernel<<<B_ * C_, 128>>>(x, pinvn);
    split_kernel<<<(B_ * C_ * F_) / 256, 256>>>(x, pxhi, pxlo);
    mma_gemm<0><<<dim3(C_ / 128, C_ / 128, B_), 256, smem4>>>(
        pxhi, pxlo, pxhi, pxlo, F_, F_, F_,
        (size_t)C_ * F_, (size_t)C_ * F_, pinvn, C_,
        pA, nullptr, C_, (size_t)C_ * C_);
    deg_kernel<<<B_ * C_, 256>>>(pA, pdinv);

    // ---- layer 1 ----
    scale_transpose<<<dim3(C_ / 32, F_ / 32, B_), dim3(32, 8)>>>(x, pdinv, phThi, phTlo);
    mma_gemm<1><<<dim3(F_ / 128, C_ / 128, B_), 256, smem3>>>(
        pA, nullptr, phThi, phTlo, C_, C_, C_,
        (size_t)C_ * C_, (size_t)F_ * C_, pdinv, C_,
        plxhi, plxlo, F_, (size_t)C_ * F_);
    wtrans_kernel<<<dim3(F_ / 32, F_ / 32), dim3(32, 8)>>>(W1, pWThi, pWTlo);
    mma_gemm<2><<<dim3(F_ / 128, (B_ * C_) / 128, 1), 256, smem4>>>(
        plxhi, plxlo, pWThi, pWTlo, F_, F_, F_,
        0, 0, b1, 0,
        ph2, nullptr, F_, 0);

    // ---- layer 2 ----
    scale_transpose<<<dim3(C_ / 32, F_ / 32, B_), dim3(32, 8)>>>(ph2, pdinv, phThi, phTlo);
    mma_gemm<1><<<dim3(F_ / 128, C_ / 128, B_), 256, smem3>>>(
        pA, nullptr, phThi, phTlo, C_, C_, C_,
        (size_t)C_ * C_, (size_t)F_ * C_, pdinv, C_,
        plxhi, plxlo, F_, (size_t)C_ * F_);
    wtrans_kernel<<<dim3(F_ / 32, F_ / 32), dim3(32, 8)>>>(W2, pWThi, pWTlo);
    mma_gemm<2><<<dim3(F_ / 128, (B_ * C_) / 128, 1), 256, smem4>>>(
        plxhi, plxlo, pWThi, pWTlo, F_, F_, F_,
        0, 0, b2, 0,
        out, nullptr, F_, 0);
}

// round 4
// speedup vs baseline: 3.5082x; 2.2265x over previous
#include <cuda_runtime.h>
#include <cuda_fp16.h>
#include <cstdint>
#include <math.h>

#define B_ 8
#define C_ 2048
#define F_ 512
#define THRESH 0.005f

// ---- scratch (device globals: no allocation allowed) ----
__device__ __half g_A[(size_t)B_ * C_ * C_];       // binary adjacency (fp16 0/1)
__device__ float  g_invn[B_ * C_];
__device__ float  g_deg[B_ * C_];
__device__ float  g_dinv[B_ * C_];
__device__ __half g_xhi[(size_t)B_ * C_ * F_];
__device__ __half g_xlo[(size_t)B_ * C_ * F_];
__device__ __half g_hT_hi[(size_t)B_ * F_ * C_];   // (dinv*h)^T split
__device__ __half g_hT_lo[(size_t)B_ * F_ * C_];
__device__ __half g_lx_hi[(size_t)B_ * C_ * F_];   // L@h split
__device__ __half g_lx_lo[(size_t)B_ * C_ * F_];
__device__ float  g_h2[(size_t)B_ * C_ * F_];      // hidden activations
__device__ __half g_WT_hi[F_ * F_];
__device__ __half g_WT_lo[F_ * F_];

// =============================== helpers ===============================
__device__ __forceinline__ uint32_t smem_u32(const void* p) {
    uint32_t a;
    asm("{ .reg .u64 t; cvta.to.shared.u64 t, %1; cvt.u32.u64 %0, t; }" : "=r"(a) : "l"(p));
    return a;
}
#define CP_COMMIT() asm volatile("cp.async.commit_group;" ::: "memory")
#define CP_WAIT1()  asm volatile("cp.async.wait_group 1;" ::: "memory")
#define CP_WAIT0()  asm volatile("cp.async.wait_group 0;" ::: "memory")

__device__ __forceinline__ void mma_f16(float c[4], const uint32_t a[4], const uint32_t b[2]) {
    asm volatile(
        "mma.sync.aligned.m16n8k16.row.col.f32.f16.f16.f32 "
        "{%0,%1,%2,%3}, {%4,%5,%6,%7}, {%8,%9}, {%0,%1,%2,%3};"
        : "+f"(c[0]), "+f"(c[1]), "+f"(c[2]), "+f"(c[3])
        : "r"(a[0]), "r"(a[1]), "r"(a[2]), "r"(a[3]), "r"(b[0]), "r"(b[1]));
}
__device__ __forceinline__ void ldsm4(uint32_t r[4], uint32_t addr) {
    asm volatile("ldmatrix.sync.aligned.m8n8.x4.shared.b16 {%0,%1,%2,%3}, [%4];"
        : "=r"(r[0]), "=r"(r[1]), "=r"(r[2]), "=r"(r[3]) : "r"(addr));
}

// ====================== fp16 mma GEMM (128x128 tile, KC=32) ======================
// All operands row-major with K contiguous: Aop[m][k] (lda), Bop[n][k] (ldb).
// MODE 0: GRAM (symmetric blocks) acc = xhi·xhiT + xhi·xloT + xlo·xhiT
//         epi: binarize corr; write tile + mirror; accumulate degrees (atomics)
// MODE 1: AH   acc = A·hThiT + A·hTloT ; epi: *dinv[m], split -> fp16 hi/lo
// MODE 2: HW   acc = 3-pass split      ; epi: relu(+bias) -> fp32
#define KC 32
#define TPAD 40                 // halves per smem tile row (conflict-free)
#define TEH (128 * TPAD)        // halves per tile

template <int MODE>
__global__ __launch_bounds__(256) void mma_gemm(
    const __half* __restrict__ a0, const __half* __restrict__ a1,
    const __half* __restrict__ b0, const __half* __restrict__ b1,
    int lda, int ldb, int K,
    size_t aBatch, size_t bBatch,
    const float* __restrict__ aux, int auxBatch,
    void* __restrict__ out0, void* __restrict__ out1,
    int ldo, size_t oBatch,
    float* __restrict__ deg)
{
    constexpr int NA = (MODE == 1) ? 1 : 2;
    constexpr int NOPS = NA + 2;

    int m0, n0, b = blockIdx.z;
    if (MODE == 0) {
        int idx = blockIdx.x, bi = 0;
        while (idx >= (C_ / 128 - bi)) { idx -= (C_ / 128 - bi); bi++; }
        m0 = bi * 128; n0 = (bi + idx) * 128;
    } else {
        m0 = blockIdx.y * 128; n0 = blockIdx.x * 128;
    }

    int tid = threadIdx.x, wid = tid >> 5, lane = tid & 31;
    int wm = wid & 1, wn = wid >> 1;          // warp tile 64x32 at (wm*64, wn*32)
    int g = lane >> 2, t = lane & 3;

    const __half* ops[NOPS];
    int ldv[NOPS];
    ops[0] = a0 + (size_t)b * aBatch + (size_t)m0 * lda; ldv[0] = lda;
    if (NA == 2) { ops[1] = a1 + (size_t)b * aBatch + (size_t)m0 * lda; ldv[1] = lda; }
    ops[NA]     = b0 + (size_t)b * bBatch + (size_t)n0 * ldb; ldv[NA] = ldb;
    ops[NA + 1] = b1 + (size_t)b * bBatch + (size_t)n0 * ldb; ldv[NA + 1] = ldb;

    extern __shared__ __half sm[];
    uint32_t smb = smem_u32(sm);

    auto load_tile = [&](int op, int buf, int k0) {
        uint32_t st = smb + (uint32_t)((buf * NOPS + op) * TEH) * 2u;
        const __half* src = ops[op] + k0;
        int ld = ldv[op];
#pragma unroll
        for (int i2 = 0; i2 < 2; i2++) {
            int idx = tid + i2 * 256;            // 0..511
            int row = idx >> 2, seg = idx & 3;
            const __half* gp = src + (size_t)row * ld + seg * 8;
            uint32_t sa = st + (uint32_t)(row * TPAD + seg * 8) * 2u;
            asm volatile("cp.async.cg.shared.global [%0], [%1], 16;" :: "r"(sa), "l"(gp) : "memory");
        }
    };

    float acc[4][4][4];
#pragma unroll
    for (int i = 0; i < 4; i++)
#pragma unroll
        for (int j = 0; j < 4; j++)
#pragma unroll
            for (int r = 0; r < 4; r++) acc[i][j][r] = 0.f;

    // ldmatrix lane->(row, kcol) offsets
    int a_row = ((lane >> 3) & 1) * 8 + (lane & 7);
    int a_kc  = (lane >> 4) * 8;
    int b_row = ((lane >> 4) & 1) * 8 + (lane & 7);
    int b_kc  = ((lane >> 3) & 1) * 8;

    uint32_t afr[2][4][4];
    uint32_t bfr[2][4][2];

    const int NC = K / KC;
    for (int op = 0; op < NOPS; op++) load_tile(op, 0, 0);
    CP_COMMIT();

    for (int c = 0; c < NC; c++) {
        int buf = c & 1;
        if (c + 1 < NC) {
            for (int op = 0; op < NOPS; op++) load_tile(op, (c + 1) & 1, (c + 1) * KC);
            CP_COMMIT();
            CP_WAIT1();
        } else {
            CP_WAIT0();
        }
        __syncthreads();
#pragma unroll
        for (int ks = 0; ks < 2; ks++) {
            int kk = ks * 16;
            uint32_t ab0 = smb + (uint32_t)((buf * NOPS + 0) * TEH + (wm * 64 + a_row) * TPAD + kk + a_kc) * 2u;
#pragma unroll
            for (int i = 0; i < 4; i++) ldsm4(afr[0][i], ab0 + (uint32_t)(i * 16 * TPAD) * 2u);
            uint32_t bb0 = smb + (uint32_t)((buf * NOPS + NA) * TEH + (wn * 32 + b_row) * TPAD + kk + b_kc) * 2u;
            ldsm4(&bfr[0][0][0], bb0);
            ldsm4(&bfr[0][2][0], bb0 + (uint32_t)(16 * TPAD) * 2u);
            uint32_t bb1 = smb + (uint32_t)((buf * NOPS + NA + 1) * TEH + (wn * 32 + b_row) * TPAD + kk + b_kc) * 2u;
            ldsm4(&bfr[1][0][0], bb1);
            ldsm4(&bfr[1][2][0], bb1 + (uint32_t)(16 * TPAD) * 2u);
            if (MODE != 1) {
                uint32_t ab1 = smb + (uint32_t)((buf * NOPS + 1) * TEH + (wm * 64 + a_row) * TPAD + kk + a_kc) * 2u;
#pragma unroll
                for (int i = 0; i < 4; i++) ldsm4(afr[1][i], ab1 + (uint32_t)(i * 16 * TPAD) * 2u);
            }
#pragma unroll
            for (int i = 0; i < 4; i++)
#pragma unroll
                for (int j = 0; j < 4; j++) mma_f16(acc[i][j], afr[0][i], bfr[0][j]);
#pragma unroll
            for (int i = 0; i < 4; i++)
#pragma unroll
                for (int j = 0; j < 4; j++) mma_f16(acc[i][j], afr[0][i], bfr[1][j]);
            if (MODE != 1) {
#pragma unroll
                for (int i = 0; i < 4; i++)
#pragma unroll
                    for (int j = 0; j < 4; j++) mma_f16(acc[i][j], afr[1][i], bfr[0][j]);
            }
        }
        __syncthreads();
    }

    // ------------------------------- epilogues -------------------------------
    if (MODE == 0) {
        const float* inb = aux + (size_t)b * auxBatch;
        __half* Ab = (__half*)out0 + (size_t)b * oBatch;
        float* degb = deg + (size_t)b * C_;
        float v[4][4][4];
#pragma unroll
        for (int i = 0; i < 4; i++) {
            int r0 = m0 + wm * 64 + i * 16 + g;
            float rs0 = inb[r0], rs1 = inb[r0 + 8];
#pragma unroll
            for (int j = 0; j < 4; j++) {
                int cl = n0 + wn * 32 + j * 8 + t * 2;
                float j0 = inb[cl], j1 = inb[cl + 1];
                v[i][j][0] = (acc[i][j][0] * rs0 * j0 > THRESH) ? 1.f : 0.f;
                v[i][j][1] = (acc[i][j][1] * rs0 * j1 > THRESH) ? 1.f : 0.f;
                v[i][j][2] = (acc[i][j][2] * rs1 * j0 > THRESH) ? 1.f : 0.f;
                v[i][j][3] = (acc[i][j][3] * rs1 * j1 > THRESH) ? 1.f : 0.f;
                *(__half2*)(Ab + (size_t)r0 * ldo + cl)       = __floats2half2_rn(v[i][j][0], v[i][j][1]);
                *(__half2*)(Ab + (size_t)(r0 + 8) * ldo + cl) = __floats2half2_rn(v[i][j][2], v[i][j][3]);
            }
        }
        // degrees: row sums (always)
#pragma unroll
        for (int i = 0; i < 4; i++) {
            float s0 = 0.f, s1 = 0.f;
#pragma unroll
            for (int j = 0; j < 4; j++) {
                s0 += v[i][j][0] + v[i][j][1];
                s1 += v[i][j][2] + v[i][j][3];
            }
            s0 += __shfl_xor_sync(0xFFFFFFFFu, s0, 1); s0 += __shfl_xor_sync(0xFFFFFFFFu, s0, 2);
            s1 += __shfl_xor_sync(0xFFFFFFFFu, s1, 1); s1 += __shfl_xor_sync(0xFFFFFFFFu, s1, 2);
            if (t == 0) {
                atomicAdd(&degb[m0 + wm * 64 + i * 16 + g], s0);
                atomicAdd(&degb[m0 + wm * 64 + i * 16 + g + 8], s1);
            }
        }
        if (m0 != n0) {
            // degrees: column sums (mirror rows)
#pragma unroll
            for (int j = 0; j < 4; j++) {
                float c0 = 0.f, c1 = 0.f;
#pragma unroll
                for (int i = 0; i < 4; i++) {
                    c0 += v[i][j][0] + v[i][j][2];
                    c1 += v[i][j][1] + v[i][j][3];
                }
                c0 += __shfl_xor_sync(0xFFFFFFFFu, c0, 4); c0 += __shfl_xor_sync(0xFFFFFFFFu, c0, 8); c0 += __shfl_xor_sync(0xFFFFFFFFu, c0, 16);
                c1 += __shfl_xor_sync(0xFFFFFFFFu, c1, 4); c1 += __shfl_xor_sync(0xFFFFFFFFu, c1, 8); c1 += __shfl_xor_sync(0xFFFFFFFFu, c1, 16);
                if (lane < 4) {
                    atomicAdd(&degb[n0 + wn * 32 + j * 8 + t * 2], c0);
                    atomicAdd(&degb[n0 + wn * 32 + j * 8 + t * 2 + 1], c1);
                }
            }
            // mirror write via smem stage (tiles are dead now)
            float* stage = (float*)sm;                 // 128 x 129 floats
#pragma unroll
            for (int i = 0; i < 4; i++) {
                int rr = wm * 64 + i * 16 + g;
#pragma unroll
                for (int j = 0; j < 4; j++) {
                    int cc = wn * 32 + j * 8 + t * 2;
                    stage[rr * 129 + cc]           = v[i][j][0];
                    stage[rr * 129 + cc + 1]       = v[i][j][1];
                    stage[(rr + 8) * 129 + cc]     = v[i][j][2];
                    stage[(rr + 8) * 129 + cc + 1] = v[i][j][3];
                }
            }
            __syncthreads();
#pragma unroll
            for (int q = 0; q < 16; q++) {
                int idx = tid + q * 256;               // 0..4095
                int r = idx >> 5;
                int c4 = (idx & 31) * 4;
                float f0 = stage[(c4 + 0) * 129 + r];
                float f1 = stage[(c4 + 1) * 129 + r];
                float f2 = stage[(c4 + 2) * 129 + r];
                float f3 = stage[(c4 + 3) * 129 + r];
                __half* dst = Ab + (size_t)(n0 + r) * ldo + m0 + c4;
                ((__half2*)dst)[0] = __floats2half2_rn(f0, f1);
                ((__half2*)dst)[1] = __floats2half2_rn(f2, f3);
            }
        }
    } else if (MODE == 1) {
        const float* db = aux + (size_t)b * auxBatch;
        __half* o0 = (__half*)out0 + (size_t)b * oBatch;
        __half* o1 = (__half*)out1 + (size_t)b * oBatch;
#pragma unroll
        for (int i = 0; i < 4; i++) {
            int r0 = m0 + wm * 64 + i * 16 + g;
            float rs0 = db[r0], rs1 = db[r0 + 8];
#pragma unroll
            for (int j = 0; j < 4; j++) {
                int cl = n0 + wn * 32 + j * 8 + t * 2;
                float v00 = acc[i][j][0] * rs0, v01 = acc[i][j][1] * rs0;
                float v10 = acc[i][j][2] * rs1, v11 = acc[i][j][3] * rs1;
                __half h00 = __float2half_rn(v00), h01 = __float2half_rn(v01);
                __half h10 = __float2half_rn(v10), h11 = __float2half_rn(v11);
                *(__half2*)(o0 + (size_t)r0 * ldo + cl)       = __halves2half2(h00, h01);
                *(__half2*)(o0 + (size_t)(r0 + 8) * ldo + cl) = __halves2half2(h10, h11);
                *(__half2*)(o1 + (size_t)r0 * ldo + cl) =
                    __floats2half2_rn(v00 - __half2float(h00), v01 - __half2float(h01));
                *(__half2*)(o1 + (size_t)(r0 + 8) * ldo + cl) =
                    __floats2half2_rn(v10 - __half2float(h10), v11 - __half2float(h11));
            }
        }
    } else {
        float bias = aux[0];
        float* o = (float*)out0;
#pragma unroll
        for (int i = 0; i < 4; i++) {
            int r0 = m0 + wm * 64 + i * 16 + g;
#pragma unroll
            for (int j = 0; j < 4; j++) {
                int cl = n0 + wn * 32 + j * 8 + t * 2;
                float v00 = fmaxf(acc[i][j][0] + bias, 0.f);
                float v01 = fmaxf(acc[i][j][1] + bias, 0.f);
                float v10 = fmaxf(acc[i][j][2] + bias, 0.f);
                float v11 = fmaxf(acc[i][j][3] + bias, 0.f);
                *(float2*)(o + (size_t)r0 * ldo + cl)       = make_float2(v00, v01);
                *(float2*)(o + (size_t)(r0 + 8) * ldo + cl) = make_float2(v10, v11);
            }
        }
    }
}

// =============================== small kernels ==============================
__global__ void zero_kernel(float* __restrict__ p) {
    p[blockIdx.x * 256 + threadIdx.x] = 0.f;
}

__global__ void norm_kernel(const float* __restrict__ x, float* __restrict__ invn) {
    int row = blockIdx.x;
    const float* xr = x + (size_t)row * F_;
    float s = 0.f;
    for (int i = threadIdx.x; i < F_; i += 128) { float v = xr[i]; s += v * v; }
    __shared__ float red[128];
    red[threadIdx.x] = s; __syncthreads();
    for (int o = 64; o > 0; o >>= 1) {
        if (threadIdx.x < o) red[threadIdx.x] += red[threadIdx.x + o];
        __syncthreads();
    }
    if (threadIdx.x == 0) invn[row] = 1.0f / sqrtf(red[0]);
}

__global__ void split_kernel(const float* __restrict__ x,
                             __half* __restrict__ hi, __half* __restrict__ lo) {
    size_t i = (size_t)blockIdx.x * 256 + threadIdx.x;
    float v = x[i];
    __half h = __float2half_rn(v);
    hi[i] = h;
    lo[i] = __float2half_rn(v - __half2float(h));
}

__global__ void dinv_kernel(const float* __restrict__ deg, float* __restrict__ dinv) {
    int i = blockIdx.x * 256 + threadIdx.x;
    dinv[i] = 1.0f / sqrtf(deg[i]);
}

// h[b,c,f] * dinv[b,c] -> transposed split hT_hi/lo [b,f,c] (fp16)
__global__ void scale_transpose(const float* __restrict__ h, const float* __restrict__ dinv,
                                __half* __restrict__ thi, __half* __restrict__ tlo) {
    __shared__ float tsm[32][33];
    int c0 = blockIdx.x * 32, f0 = blockIdx.y * 32, b = blockIdx.z;
    const float* hb = h + (size_t)b * C_ * F_;
#pragma unroll
    for (int k = 0; k < 4; k++) {
        int c = c0 + threadIdx.y + k * 8;
        float v = hb[(size_t)c * F_ + f0 + threadIdx.x] * dinv[b * C_ + c];
        tsm[threadIdx.x][threadIdx.y + k * 8] = v;
    }
    __syncthreads();
#pragma unroll
    for (int k = 0; k < 4; k++) {
        int f = f0 + threadIdx.y + k * 8;
        float v = tsm[threadIdx.y + k * 8][threadIdx.x];
        __half hh = __float2half_rn(v);
        size_t o = (size_t)b * F_ * C_ + (size_t)f * C_ + c0 + threadIdx.x;
        thi[o] = hh;
        tlo[o] = __float2half_rn(v - __half2float(hh));
    }
}

// W[f,g] -> WT[g,f] split (fp16)
__global__ void wtrans_kernel(const float* __restrict__ W,
                              __half* __restrict__ hi, __half* __restrict__ lo) {
    __shared__ float tsm[32][33];
    int g0 = blockIdx.x * 32, f0 = blockIdx.y * 32;
#pragma unroll
    for (int k = 0; k < 4; k++) {
        int f = f0 + threadIdx.y + k * 8;
        tsm[threadIdx.x][threadIdx.y + k * 8] = W[(size_t)f * F_ + g0 + threadIdx.x];
    }
    __syncthreads();
#pragma unroll
    for (int k = 0; k < 4; k++) {
        int gg = g0 + threadIdx.y + k * 8;
        float v = tsm[threadIdx.y + k * 8][threadIdx.x];
        __half hh = __float2half_rn(v);
        size_t o = (size_t)gg * F_ + f0 + threadIdx.x;
        hi[o] = hh;
        lo[o] = __float2half_rn(v - __half2float(hh));
    }
}

// ============================================================================
extern "C" void kernel_launch(void* const* d_in, const int* in_sizes, int n_in,
                              void* d_out, int out_size) {
    const float* x  = (const float*)d_in[0];
    const float* W1 = (const float*)d_in[1];
    const float* b1 = (const float*)d_in[2];
    const float* W2 = (const float*)d_in[3];
    const float* b2 = (const float*)d_in[4];
    float* out = (float*)d_out;

    __half *pA, *pxhi, *pxlo, *phThi, *phTlo, *plxhi, *plxlo, *pWThi, *pWTlo;
    float *pinvn, *pdeg, *pdinv, *ph2;
    cudaGetSymbolAddress((void**)&pA,    g_A);
    cudaGetSymbolAddress((void**)&pinvn, g_invn);
    cudaGetSymbolAddress((void**)&pdeg,  g_deg);
    cudaGetSymbolAddress((void**)&pdinv, g_dinv);
    cudaGetSymbolAddress((void**)&pxhi,  g_xhi);
    cudaGetSymbolAddress((void**)&pxlo,  g_xlo);
    cudaGetSymbolAddress((void**)&phThi, g_hT_hi);
    cudaGetSymbolAddress((void**)&phTlo, g_hT_lo);
    cudaGetSymbolAddress((void**)&plxhi, g_lx_hi);
    cudaGetSymbolAddress((void**)&plxlo, g_lx_lo);
    cudaGetSymbolAddress((void**)&ph2,   g_h2);
    cudaGetSymbolAddress((void**)&pWThi, g_WT_hi);
    cudaGetSymbolAddress((void**)&pWTlo, g_WT_lo);

    const int smem4 = 4 * 2 * TEH * 2;   // 81920 B (GRAM / HW)
    const int smem3 = 3 * 2 * TEH * 2;   // 61440 B (AH)
    cudaFuncSetAttribute(mma_gemm<0>, cudaFuncAttributeMaxDynamicSharedMemorySize, smem4);
    cudaFuncSetAttribute(mma_gemm<1>, cudaFuncAttributeMaxDynamicSharedMemorySize, smem3);
    cudaFuncSetAttribute(mma_gemm<2>, cudaFuncAttributeMaxDynamicSharedMemorySize, smem4);

    const int NBLK = C_ / 128;                       // 16
    const int NTRI = NBLK * (NBLK + 1) / 2;          // 136

    // ---- Laplacian ----
    zero_kernel<<<(B_ * C_) / 256, 256>>>(pdeg);
    norm_kernel<<<B_ * C_, 128>>>(x, pinvn);
    split_kernel<<<(B_ * C_ * F_) / 256, 256>>>(x, pxhi, pxlo);
    mma_gemm<0><<<dim3(NTRI, 1, B_), 256, smem4>>>(
        pxhi, pxlo, pxhi, pxlo, F_, F_, F_,
        (size_t)C_ * F_, (size_t)C_ * F_, pinvn, C_,
        pA, nullptr, C_, (size_t)C_ * C_, pdeg);
    dinv_kernel<<<(B_ * C_) / 256, 256>>>(pdeg, pdinv);

    // ---- layer 1 ----
    scale_transpose<<<dim3(C_ / 32, F_ / 32, B_), dim3(32, 8)>>>(x, pdinv, phThi, phTlo);
    mma_gemm<1><<<dim3(F_ / 128, C_ / 128, B_), 256, smem3>>>(
        pA, nullptr, phThi, phTlo, C_, C_, C_,
        (size_t)C_ * C_, (size_t)F_ * C_, pdinv, C_,
        plxhi, plxlo, F_, (size_t)C_ * F_, nullptr);
    wtrans_kernel<<<dim3(F_ / 32, F_ / 32), dim3(32, 8)>>>(W1, pWThi, pWTlo);
    mma_gemm<2><<<dim3(F_ / 128, (B_ * C_) / 128, 1), 256, smem4>>>(
        plxhi, plxlo, pWThi, pWTlo, F_, F_, F_,
        0, 0, b1, 0,
        ph2, nullptr, F_, 0, nullptr);

    // ---- layer 2 ----
    scale_transpose<<<dim3(C_ / 32, F_ / 32, B_), dim3(32, 8)>>>(ph2, pdinv, phThi, phTlo);
    mma_gemm<1><<<dim3(F_ / 128, C_ / 128, B_), 256, smem3>>>(
        pA, nullptr, phThi, phTlo, C_, C_, C_,
        (size_t)C_ * C_, (size_t)F_ * C_, pdinv, C_,
        plxhi, plxlo, F_, (size_t)C_ * F_, nullptr);
    wtrans_kernel<<<dim3(F_ / 32, F_ / 32), dim3(32, 8)>>>(W2, pWThi, pWTlo);
    mma_gemm<2><<<dim3(F_ / 128, (B_ * C_) / 128, 1), 256, smem4>>>(
        plxhi, plxlo, pWThi, pWTlo, F_, F_, F_,
        0, 0, b2, 0,
        out, nullptr, F_, 0, nullptr);
}

// round 5
// speedup vs baseline: 3.7276x; 1.0625x over previous
#include <cuda_runtime.h>
#include <cuda_fp16.h>
#include <cstdint>
#include <math.h>

#define B_ 8
#define C_ 2048
#define F_ 512
#define THRESH 0.005f

// ---- scratch (device globals: no allocation allowed) ----
__device__ __half g_A[(size_t)B_ * C_ * C_];       // binary adjacency (fp16 0/1)
__device__ float  g_invn[B_ * C_];
__device__ float  g_deg[B_ * C_];
__device__ float  g_dinv[B_ * C_];
__device__ __half g_xhi[(size_t)B_ * C_ * F_];
__device__ __half g_xlo[(size_t)B_ * C_ * F_];
__device__ __half g_hT_hi[(size_t)B_ * F_ * C_];   // (dinv*h)^T split
__device__ __half g_hT_lo[(size_t)B_ * F_ * C_];
__device__ __half g_lx_hi[(size_t)B_ * C_ * F_];   // L@h split
__device__ __half g_lx_lo[(size_t)B_ * C_ * F_];
__device__ float  g_h2[(size_t)B_ * C_ * F_];      // hidden activations
__device__ __half g_WT_hi[F_ * F_];
__device__ __half g_WT_lo[F_ * F_];

// =============================== helpers ===============================
__device__ __forceinline__ uint32_t smem_u32(const void* p) {
    uint32_t a;
    asm("{ .reg .u64 t; cvta.to.shared.u64 t, %1; cvt.u32.u64 %0, t; }" : "=r"(a) : "l"(p));
    return a;
}
#define CP_COMMIT() asm volatile("cp.async.commit_group;" ::: "memory")
#define CP_WAIT1()  asm volatile("cp.async.wait_group 1;" ::: "memory")
#define CP_WAIT0()  asm volatile("cp.async.wait_group 0;" ::: "memory")

__device__ __forceinline__ void mma_f16(float c[4], const uint32_t a[4], const uint32_t b[2]) {
    asm volatile(
        "mma.sync.aligned.m16n8k16.row.col.f32.f16.f16.f32 "
        "{%0,%1,%2,%3}, {%4,%5,%6,%7}, {%8,%9}, {%0,%1,%2,%3};"
        : "+f"(c[0]), "+f"(c[1]), "+f"(c[2]), "+f"(c[3])
        : "r"(a[0]), "r"(a[1]), "r"(a[2]), "r"(a[3]), "r"(b[0]), "r"(b[1]));
}
__device__ __forceinline__ void ldsm4(uint32_t r[4], uint32_t addr) {
    asm volatile("ldmatrix.sync.aligned.m8n8.x4.shared.b16 {%0,%1,%2,%3}, [%4];"
        : "=r"(r[0]), "=r"(r[1]), "=r"(r[2]), "=r"(r[3]) : "r"(addr));
}

// ====================== fp16 mma GEMM (128x128 tile, KC=32) ======================
// All operands row-major with K contiguous: Aop[m][k] (lda), Bop[n][k] (ldb).
// MODE 0: GRAM (symmetric blocks) acc = xhi·xhiT + xhi·xloT + xlo·xhiT
// MODE 1: AH   acc = A·hThiT + A·hTloT ; epi: *dinv[m], split -> fp16 hi/lo
// MODE 2: HW   acc = 3-pass split      ; epi: relu(+bias) -> fp32
#define KC 32
#define TPAD 40                 // halves per smem tile row (conflict-free)
#define TEH (128 * TPAD)        // halves per tile

template <int MODE>
__global__ __launch_bounds__(256, 2) void mma_gemm(
    const __half* __restrict__ a0, const __half* __restrict__ a1,
    const __half* __restrict__ b0, const __half* __restrict__ b1,
    int lda, int ldb, int K,
    size_t aBatch, size_t bBatch,
    const float* __restrict__ aux, int auxBatch,
    void* __restrict__ out0, void* __restrict__ out1,
    int ldo, size_t oBatch,
    float* __restrict__ deg)
{
    constexpr int NA = (MODE == 1) ? 1 : 2;
    constexpr int NOPS = NA + 2;

    int m0, n0, b = blockIdx.z;
    if (MODE == 0) {
        int idx = blockIdx.x, bi = 0;
        while (idx >= (C_ / 128 - bi)) { idx -= (C_ / 128 - bi); bi++; }
        m0 = bi * 128; n0 = (bi + idx) * 128;
    } else {
        m0 = blockIdx.y * 128; n0 = blockIdx.x * 128;
    }

    int tid = threadIdx.x, wid = tid >> 5, lane = tid & 31;
    int wm = wid & 1, wn = wid >> 1;          // warp tile 64x32 at (wm*64, wn*32)
    int g = lane >> 2, t = lane & 3;

    const __half* ops[NOPS];
    int ldv[NOPS];
    ops[0] = a0 + (size_t)b * aBatch + (size_t)m0 * lda; ldv[0] = lda;
    if (NA == 2) { ops[1] = a1 + (size_t)b * aBatch + (size_t)m0 * lda; ldv[1] = lda; }
    ops[NA]     = b0 + (size_t)b * bBatch + (size_t)n0 * ldb; ldv[NA] = ldb;
    ops[NA + 1] = b1 + (size_t)b * bBatch + (size_t)n0 * ldb; ldv[NA + 1] = ldb;

    extern __shared__ __half sm[];
    uint32_t smb = smem_u32(sm);

    auto load_tile = [&](int op, int buf, int k0) {
        uint32_t st = smb + (uint32_t)((buf * NOPS + op) * TEH) * 2u;
        const __half* src = ops[op] + k0;
        int ld = ldv[op];
#pragma unroll
        for (int i2 = 0; i2 < 2; i2++) {
            int idx = tid + i2 * 256;            // 0..511
            int row = idx >> 2, seg = idx & 3;
            const __half* gp = src + (size_t)row * ld + seg * 8;
            uint32_t sa = st + (uint32_t)(row * TPAD + seg * 8) * 2u;
            asm volatile("cp.async.cg.shared.global [%0], [%1], 16;" :: "r"(sa), "l"(gp) : "memory");
        }
    };

    float acc[4][4][4];
#pragma unroll
    for (int i = 0; i < 4; i++)
#pragma unroll
        for (int j = 0; j < 4; j++)
#pragma unroll
            for (int r = 0; r < 4; r++) acc[i][j][r] = 0.f;

    // ldmatrix lane->(row, kcol) offsets
    int a_row = ((lane >> 3) & 1) * 8 + (lane & 7);
    int a_kc  = (lane >> 4) * 8;
    int b_row = ((lane >> 4) & 1) * 8 + (lane & 7);
    int b_kc  = ((lane >> 3) & 1) * 8;

    uint32_t afr[NA][4][4];     // all A operand frags stay live
    uint32_t bfr[4][2];         // one B slot, reloaded per pass

    const int NC = K / KC;
    for (int op = 0; op < NOPS; op++) load_tile(op, 0, 0);
    CP_COMMIT();

    for (int c = 0; c < NC; c++) {
        int buf = c & 1;
        if (c + 1 < NC) {
            for (int op = 0; op < NOPS; op++) load_tile(op, (c + 1) & 1, (c + 1) * KC);
            CP_COMMIT();
            CP_WAIT1();
        } else {
            CP_WAIT0();
        }
        __syncthreads();
#pragma unroll
        for (int ks = 0; ks < 2; ks++) {
            int kk = ks * 16;
            uint32_t ab0 = smb + (uint32_t)((buf * NOPS + 0) * TEH + (wm * 64 + a_row) * TPAD + kk + a_kc) * 2u;
#pragma unroll
            for (int i = 0; i < 4; i++) ldsm4(afr[0][i], ab0 + (uint32_t)(i * 16 * TPAD) * 2u);
            if (MODE != 1) {
                uint32_t ab1 = smb + (uint32_t)((buf * NOPS + 1) * TEH + (wm * 64 + a_row) * TPAD + kk + a_kc) * 2u;
#pragma unroll
                for (int i = 0; i < 4; i++) ldsm4(afr[NA - 1][i], ab1 + (uint32_t)(i * 16 * TPAD) * 2u);
            }
            // B0 passes: A0*B0 (+ A1*B0)
            uint32_t bb0 = smb + (uint32_t)((buf * NOPS + NA) * TEH + (wn * 32 + b_row) * TPAD + kk + b_kc) * 2u;
            ldsm4(&bfr[0][0], bb0);
            ldsm4(&bfr[2][0], bb0 + (uint32_t)(16 * TPAD) * 2u);
#pragma unroll
            for (int i = 0; i < 4; i++)
#pragma unroll
                for (int j = 0; j < 4; j++) mma_f16(acc[i][j], afr[0][i], bfr[j]);
            if (MODE != 1) {
#pragma unroll
                for (int i = 0; i < 4; i++)
#pragma unroll
                    for (int j = 0; j < 4; j++) mma_f16(acc[i][j], afr[NA - 1][i], bfr[j]);
            }
            // B1 pass: A0*B1 (reload B slot)
            uint32_t bb1 = smb + (uint32_t)((buf * NOPS + NA + 1) * TEH + (wn * 32 + b_row) * TPAD + kk + b_kc) * 2u;
            ldsm4(&bfr[0][0], bb1);
            ldsm4(&bfr[2][0], bb1 + (uint32_t)(16 * TPAD) * 2u);
#pragma unroll
            for (int i = 0; i < 4; i++)
#pragma unroll
                for (int j = 0; j < 4; j++) mma_f16(acc[i][j], afr[0][i], bfr[j]);
        }
        __syncthreads();
    }

    // ------------------------------- epilogues -------------------------------
    if (MODE == 0) {
        const float* inb = aux + (size_t)b * auxBatch;
        __half* Ab = (__half*)out0 + (size_t)b * oBatch;
        float* degb = deg + (size_t)b * C_;
        float v[4][4][4];
#pragma unroll
        for (int i = 0; i < 4; i++) {
            int r0 = m0 + wm * 64 + i * 16 + g;
            float rs0 = inb[r0], rs1 = inb[r0 + 8];
#pragma unroll
            for (int j = 0; j < 4; j++) {
                int cl = n0 + wn * 32 + j * 8 + t * 2;
                float j0 = inb[cl], j1 = inb[cl + 1];
                v[i][j][0] = (acc[i][j][0] * rs0 * j0 > THRESH) ? 1.f : 0.f;
                v[i][j][1] = (acc[i][j][1] * rs0 * j1 > THRESH) ? 1.f : 0.f;
                v[i][j][2] = (acc[i][j][2] * rs1 * j0 > THRESH) ? 1.f : 0.f;
                v[i][j][3] = (acc[i][j][3] * rs1 * j1 > THRESH) ? 1.f : 0.f;
                *(__half2*)(Ab + (size_t)r0 * ldo + cl)       = __floats2half2_rn(v[i][j][0], v[i][j][1]);
                *(__half2*)(Ab + (size_t)(r0 + 8) * ldo + cl) = __floats2half2_rn(v[i][j][2], v[i][j][3]);
            }
        }
        // degrees: row sums (always)
#pragma unroll
        for (int i = 0; i < 4; i++) {
            float s0 = 0.f, s1 = 0.f;
#pragma unroll
            for (int j = 0; j < 4; j++) {
                s0 += v[i][j][0] + v[i][j][1];
                s1 += v[i][j][2] + v[i][j][3];
            }
            s0 += __shfl_xor_sync(0xFFFFFFFFu, s0, 1); s0 += __shfl_xor_sync(0xFFFFFFFFu, s0, 2);
            s1 += __shfl_xor_sync(0xFFFFFFFFu, s1, 1); s1 += __shfl_xor_sync(0xFFFFFFFFu, s1, 2);
            if (t == 0) {
                atomicAdd(&degb[m0 + wm * 64 + i * 16 + g], s0);
                atomicAdd(&degb[m0 + wm * 64 + i * 16 + g + 8], s1);
            }
        }
        if (m0 != n0) {
            // degrees: column sums (mirror rows)
#pragma unroll
            for (int j = 0; j < 4; j++) {
                float c0 = 0.f, c1 = 0.f;
#pragma unroll
                for (int i = 0; i < 4; i++) {
                    c0 += v[i][j][0] + v[i][j][2];
                    c1 += v[i][j][1] + v[i][j][3];
                }
                c0 += __shfl_xor_sync(0xFFFFFFFFu, c0, 4); c0 += __shfl_xor_sync(0xFFFFFFFFu, c0, 8); c0 += __shfl_xor_sync(0xFFFFFFFFu, c0, 16);
                c1 += __shfl_xor_sync(0xFFFFFFFFu, c1, 4); c1 += __shfl_xor_sync(0xFFFFFFFFu, c1, 8); c1 += __shfl_xor_sync(0xFFFFFFFFu, c1, 16);
                if (lane < 4) {
                    atomicAdd(&degb[n0 + wn * 32 + j * 8 + t * 2], c0);
                    atomicAdd(&degb[n0 + wn * 32 + j * 8 + t * 2 + 1], c1);
                }
            }
            // mirror write via smem stage (tiles are dead now)
            float* stage = (float*)sm;                 // 128 x 129 floats
#pragma unroll
            for (int i = 0; i < 4; i++) {
                int rr = wm * 64 + i * 16 + g;
#pragma unroll
                for (int j = 0; j < 4; j++) {
                    int cc = wn * 32 + j * 8 + t * 2;
                    stage[rr * 129 + cc]           = v[i][j][0];
                    stage[rr * 129 + cc + 1]       = v[i][j][1];
                    stage[(rr + 8) * 129 + cc]     = v[i][j][2];
                    stage[(rr + 8) * 129 + cc + 1] = v[i][j][3];
                }
            }
            __syncthreads();
#pragma unroll
            for (int q = 0; q < 16; q++) {
                int idx = tid + q * 256;               // 0..4095
                int r = idx >> 5;
                int c4 = (idx & 31) * 4;
                float f0 = stage[(c4 + 0) * 129 + r];
                float f1 = stage[(c4 + 1) * 129 + r];
                float f2 = stage[(c4 + 2) * 129 + r];
                float f3 = stage[(c4 + 3) * 129 + r];
                __half* dst = Ab + (size_t)(n0 + r) * ldo + m0 + c4;
                ((__half2*)dst)[0] = __floats2half2_rn(f0, f1);
                ((__half2*)dst)[1] = __floats2half2_rn(f2, f3);
            }
        }
    } else if (MODE == 1) {
        const float* db = aux + (size_t)b * auxBatch;
        __half* o0 = (__half*)out0 + (size_t)b * oBatch;
        __half* o1 = (__half*)out1 + (size_t)b * oBatch;
#pragma unroll
        for (int i = 0; i < 4; i++) {
            int r0 = m0 + wm * 64 + i * 16 + g;
            float rs0 = db[r0], rs1 = db[r0 + 8];
#pragma unroll
            for (int j = 0; j < 4; j++) {
                int cl = n0 + wn * 32 + j * 8 + t * 2;
                float v00 = acc[i][j][0] * rs0, v01 = acc[i][j][1] * rs0;
                float v10 = acc[i][j][2] * rs1, v11 = acc[i][j][3] * rs1;
                __half h00 = __float2half_rn(v00), h01 = __float2half_rn(v01);
                __half h10 = __float2half_rn(v10), h11 = __float2half_rn(v11);
                *(__half2*)(o0 + (size_t)r0 * ldo + cl)       = __halves2half2(h00, h01);
                *(__half2*)(o0 + (size_t)(r0 + 8) * ldo + cl) = __halves2half2(h10, h11);
                *(__half2*)(o1 + (size_t)r0 * ldo + cl) =
                    __floats2half2_rn(v00 - __half2float(h00), v01 - __half2float(h01));
                *(__half2*)(o1 + (size_t)(r0 + 8) * ldo + cl) =
                    __floats2half2_rn(v10 - __half2float(h10), v11 - __half2float(h11));
            }
        }
    } else {
        float bias = aux[0];
        float* o = (float*)out0;
#pragma unroll
        for (int i = 0; i < 4; i++) {
            int r0 = m0 + wm * 64 + i * 16 + g;
#pragma unroll
            for (int j = 0; j < 4; j++) {
                int cl = n0 + wn * 32 + j * 8 + t * 2;
                float v00 = fmaxf(acc[i][j][0] + bias, 0.f);
                float v01 = fmaxf(acc[i][j][1] + bias, 0.f);
                float v10 = fmaxf(acc[i][j][2] + bias, 0.f);
                float v11 = fmaxf(acc[i][j][3] + bias, 0.f);
                *(float2*)(o + (size_t)r0 * ldo + cl)       = make_float2(v00, v01);
                *(float2*)(o + (size_t)(r0 + 8) * ldo + cl) = make_float2(v10, v11);
            }
        }
    }
}

// =============================== small kernels ==============================
__global__ void zero_kernel(float* __restrict__ p) {
    p[blockIdx.x * 256 + threadIdx.x] = 0.f;
}

__global__ void norm_kernel(const float* __restrict__ x, float* __restrict__ invn) {
    int row = blockIdx.x;
    const float* xr = x + (size_t)row * F_;
    float s = 0.f;
    for (int i = threadIdx.x; i < F_; i += 128) { float v = xr[i]; s += v * v; }
    __shared__ float red[128];
    red[threadIdx.x] = s; __syncthreads();
    for (int o = 64; o > 0; o >>= 1) {
        if (threadIdx.x < o) red[threadIdx.x] += red[threadIdx.x + o];
        __syncthreads();
    }
    if (threadIdx.x == 0) invn[row] = 1.0f / sqrtf(red[0]);
}

__global__ void split_kernel(const float* __restrict__ x,
                             __half* __restrict__ hi, __half* __restrict__ lo) {
    size_t i = (size_t)blockIdx.x * 256 + threadIdx.x;
    float v = x[i];
    __half h = __float2half_rn(v);
    hi[i] = h;
    lo[i] = __float2half_rn(v - __half2float(h));
}

__global__ void dinv_kernel(const float* __restrict__ deg, float* __restrict__ dinv) {
    int i = blockIdx.x * 256 + threadIdx.x;
    dinv[i] = 1.0f / sqrtf(deg[i]);
}

// h[b,c,f] * dinv[b,c] -> transposed split hT_hi/lo [b,f,c] (fp16)
__global__ void scale_transpose(const float* __restrict__ h, const float* __restrict__ dinv,
                                __half* __restrict__ thi, __half* __restrict__ tlo) {
    __shared__ float tsm[32][33];
    int c0 = blockIdx.x * 32, f0 = blockIdx.y * 32, b = blockIdx.z;
    const float* hb = h + (size_t)b * C_ * F_;
#pragma unroll
    for (int k = 0; k < 4; k++) {
        int c = c0 + threadIdx.y + k * 8;
        float v = hb[(size_t)c * F_ + f0 + threadIdx.x] * dinv[b * C_ + c];
        tsm[threadIdx.x][threadIdx.y + k * 8] = v;
    }
    __syncthreads();
#pragma unroll
    for (int k = 0; k < 4; k++) {
        int f = f0 + threadIdx.y + k * 8;
        float v = tsm[threadIdx.y + k * 8][threadIdx.x];
        __half hh = __float2half_rn(v);
        size_t o = (size_t)b * F_ * C_ + (size_t)f * C_ + c0 + threadIdx.x;
        thi[o] = hh;
        tlo[o] = __float2half_rn(v - __half2float(hh));
    }
}

// W[f,g] -> WT[g,f] split (fp16)
__global__ void wtrans_kernel(const float* __restrict__ W,
                              __half* __restrict__ hi, __half* __restrict__ lo) {
    __shared__ float tsm[32][33];
    int g0 = blockIdx.x * 32, f0 = blockIdx.y * 32;
#pragma unroll
    for (int k = 0; k < 4; k++) {
        int f = f0 + threadIdx.y + k * 8;
        tsm[threadIdx.x][threadIdx.y + k * 8] = W[(size_t)f * F_ + g0 + threadIdx.x];
    }
    __syncthreads();
#pragma unroll
    for (int k = 0; k < 4; k++) {
        int gg = g0 + threadIdx.y + k * 8;
        float v = tsm[threadIdx.y + k * 8][threadIdx.x];
        __half hh = __float2half_rn(v);
        size_t o = (size_t)gg * F_ + f0 + threadIdx.x;
        hi[o] = hh;
        lo[o] = __float2half_rn(v - __half2float(hh));
    }
}

// ============================================================================
extern "C" void kernel_launch(void* const* d_in, const int* in_sizes, int n_in,
                              void* d_out, int out_size) {
    const float* x  = (const float*)d_in[0];
    const float* W1 = (const float*)d_in[1];
    const float* b1 = (const float*)d_in[2];
    const float* W2 = (const float*)d_in[3];
    const float* b2 = (const float*)d_in[4];
    float* out = (float*)d_out;

    __half *pA, *pxhi, *pxlo, *phThi, *phTlo, *plxhi, *plxlo, *pWThi, *pWTlo;
    float *pinvn, *pdeg, *pdinv, *ph2;
    cudaGetSymbolAddress((void**)&pA,    g_A);
    cudaGetSymbolAddress((void**)&pinvn, g_invn);
    cudaGetSymbolAddress((void**)&pdeg,  g_deg);
    cudaGetSymbolAddress((void**)&pdinv, g_dinv);
    cudaGetSymbolAddress((void**)&pxhi,  g_xhi);
    cudaGetSymbolAddress((void**)&pxlo,  g_xlo);
    cudaGetSymbolAddress((void**)&phThi, g_hT_hi);
    cudaGetSymbolAddress((void**)&phTlo, g_hT_lo);
    cudaGetSymbolAddress((void**)&plxhi, g_lx_hi);
    cudaGetSymbolAddress((void**)&plxlo, g_lx_lo);
    cudaGetSymbolAddress((void**)&ph2,   g_h2);
    cudaGetSymbolAddress((void**)&pWThi, g_WT_hi);
    cudaGetSymbolAddress((void**)&pWTlo, g_WT_lo);

    const int smem4 = 4 * 2 * TEH * 2;   // 81920 B (GRAM / HW)
    const int smem3 = 3 * 2 * TEH * 2;   // 61440 B (AH)
    cudaFuncSetAttribute(mma_gemm<0>, cudaFuncAttributeMaxDynamicSharedMemorySize, smem4);
    cudaFuncSetAttribute(mma_gemm<1>, cudaFuncAttributeMaxDynamicSharedMemorySize, smem3);
    cudaFuncSetAttribute(mma_gemm<2>, cudaFuncAttributeMaxDynamicSharedMemorySize, smem4);

    const int NBLK = C_ / 128;                       // 16
    const int NTRI = NBLK * (NBLK + 1) / 2;          // 136

    // ---- Laplacian ----
    zero_kernel<<<(B_ * C_) / 256, 256>>>(pdeg);
    norm_kernel<<<B_ * C_, 128>>>(x, pinvn);
    split_kernel<<<(B_ * C_ * F_) / 256, 256>>>(x, pxhi, pxlo);
    mma_gemm<0><<<dim3(NTRI, 1, B_), 256, smem4>>>(
        pxhi, pxlo, pxhi, pxlo, F_, F_, F_,
        (size_t)C_ * F_, (size_t)C_ * F_, pinvn, C_,
        pA, nullptr, C_, (size_t)C_ * C_, pdeg);
    dinv_kernel<<<(B_ * C_) / 256, 256>>>(pdeg, pdinv);

    // ---- layer 1 ----
    scale_transpose<<<dim3(C_ / 32, F_ / 32, B_), dim3(32, 8)>>>(x, pdinv, phThi, phTlo);
    mma_gemm<1><<<dim3(F_ / 128, C_ / 128, B_), 256, smem3>>>(
        pA, nullptr, phThi, phTlo, C_, C_, C_,
        (size_t)C_ * C_, (size_t)F_ * C_, pdinv, C_,
        plxhi, plxlo, F_, (size_t)C_ * F_, nullptr);
    wtrans_kernel<<<dim3(F_ / 32, F_ / 32), dim3(32, 8)>>>(W1, pWThi, pWTlo);
    mma_gemm<2><<<dim3(F_ / 128, (B_ * C_) / 128, 1), 256, smem4>>>(
        plxhi, plxlo, pWThi, pWTlo, F_, F_, F_,
        0, 0, b1, 0,
        ph2, nullptr, F_, 0, nullptr);

    // ---- layer 2 ----
    scale_transpose<<<dim3(C_ / 32, F_ / 32, B_), dim3(32, 8)>>>(ph2, pdinv, phThi, phTlo);
    mma_gemm<1><<<dim3(F_ / 128, C_ / 128, B_), 256, smem3>>>(
        pA, nullptr, phThi, phTlo, C_, C_, C_,
        (size_t)C_ * C_, (size_t)F_ * C_, pdinv, C_,
        plxhi, plxlo, F_, (size_t)C_ * F_, nullptr);
    wtrans_kernel<<<dim3(F_ / 32, F_ / 32), dim3(32, 8)>>>(W2, pWThi, pWTlo);
    mma_gemm<2><<<dim3(F_ / 128, (B_ * C_) / 128, 1), 256, smem4>>>(
        plxhi, plxlo, pWThi, pWTlo, F_, F_, F_,
        0, 0, b2, 0,
        out, nullptr, F_, 0, nullptr);
}